// round 4
// baseline (speedup 1.0000x reference)
#include <cuda_runtime.h>
#include <cuda_fp16.h>
#include <cstdint>
#include <cstddef>

// Problem dims
#define DI    4096
#define MROWS 8192          // 4*2048
#define NOUT  4096
#define WN    (4096*4096)

// GEMM tiling (legacy mma.sync path — tcgen05 unavailable at compute_103)
#define BM 128
#define BN 256
#define BK 64               // 64 fp16 = 128B rows -> conflict-free 128B xor swizzle
#define NSTG 3
#define NCHUNK (DI/BK)      // 64
#define A_BYTES (BM*BK*2)   // 16384
#define B_BYTES (BN*BK*2)   // 32768
#define STAGE_BYTES (A_BYTES + B_BYTES)          // 49152
#define SMEM_TOTAL (NSTG*STAGE_BYTES)            // 147456

// Scratch (no cudaMalloc allowed)
__device__ __half g_xn[(size_t)MROWS * DI];   // 64 MB fp16 layernormed x
__device__ __half g_wb[(size_t)WN];           // 32 MB fp16 binarized weight
__device__ float  g_part1[2048];
__device__ float  g_part2[2048];
__device__ float  g_wmean;
__device__ float  g_beta;

// ---------------- reduction helpers ----------------
__device__ __forceinline__ float warp_sum(float v) {
#pragma unroll
    for (int o = 16; o > 0; o >>= 1) v += __shfl_xor_sync(0xFFFFFFFFu, v, o);
    return v;
}

// ---------------- preprocessing kernels ----------------
__global__ void k_wsum(const float* __restrict__ w) {
    float s = 0.f;
    const float4* w4 = (const float4*)w;
    for (int i = blockIdx.x * 256 + threadIdx.x; i < WN / 4; i += 2048 * 256) {
        float4 v = w4[i];
        s += v.x + v.y + v.z + v.w;
    }
    __shared__ float sh[8];
    s = warp_sum(s);
    if ((threadIdx.x & 31) == 0) sh[threadIdx.x >> 5] = s;
    __syncthreads();
    if (threadIdx.x < 8) {
        float t = sh[threadIdx.x];
#pragma unroll
        for (int o = 4; o > 0; o >>= 1) t += __shfl_xor_sync(0xFFu, t, o);
        if (threadIdx.x == 0) g_part1[blockIdx.x] = t;
    }
}

__global__ void k_reduce_mean() {
    float s = 0.f;
    for (int i = threadIdx.x; i < 2048; i += 256) s += g_part1[i];
    __shared__ float sh[8];
    s = warp_sum(s);
    if ((threadIdx.x & 31) == 0) sh[threadIdx.x >> 5] = s;
    __syncthreads();
    if (threadIdx.x == 0) {
        float t = 0.f;
        for (int i = 0; i < 8; i++) t += sh[i];
        g_wmean = t / (float)WN;
    }
}

__global__ void k_binabs(const float* __restrict__ w) {
    const float m = g_wmean;
    float s = 0.f;
    const float4* w4 = (const float4*)w;
    __half2* o = (__half2*)g_wb;
    for (int i = blockIdx.x * 256 + threadIdx.x; i < WN / 4; i += 2048 * 256) {
        float4 v = w4[i];
        float a = v.x - m, b = v.y - m, c = v.z - m, d = v.w - m;
        s += fabsf(a) + fabsf(b) + fabsf(c) + fabsf(d);
        float sa = (a > 0.f) ? 1.f : ((a < 0.f) ? -1.f : 0.f);
        float sb = (b > 0.f) ? 1.f : ((b < 0.f) ? -1.f : 0.f);
        float sc = (c > 0.f) ? 1.f : ((c < 0.f) ? -1.f : 0.f);
        float sd = (d > 0.f) ? 1.f : ((d < 0.f) ? -1.f : 0.f);
        o[2 * i]     = __floats2half2_rn(sa, sb);
        o[2 * i + 1] = __floats2half2_rn(sc, sd);
    }
    __shared__ float sh[8];
    s = warp_sum(s);
    if ((threadIdx.x & 31) == 0) sh[threadIdx.x >> 5] = s;
    __syncthreads();
    if (threadIdx.x == 0) {
        float t = 0.f;
        for (int i = 0; i < 8; i++) t += sh[i];
        g_part2[blockIdx.x] = t;
    }
}

__global__ void k_reduce_beta() {
    float s = 0.f;
    for (int i = threadIdx.x; i < 2048; i += 256) s += g_part2[i];
    __shared__ float sh[8];
    s = warp_sum(s);
    if ((threadIdx.x & 31) == 0) sh[threadIdx.x >> 5] = s;
    __syncthreads();
    if (threadIdx.x == 0) {
        float t = 0.f;
        for (int i = 0; i < 8; i++) t += sh[i];
        g_beta = t / (float)WN;
    }
}

__global__ void k_ln(const float* __restrict__ x) {
    const int row = blockIdx.x;
    const float4* xr = (const float4*)(x + (size_t)row * DI);
    float4 v[4];
    float s = 0.f, ss = 0.f;
#pragma unroll
    for (int i = 0; i < 4; i++) {
        v[i] = xr[threadIdx.x + i * 256];
        s  += v[i].x + v[i].y + v[i].z + v[i].w;
        ss += v[i].x * v[i].x + v[i].y * v[i].y + v[i].z * v[i].z + v[i].w * v[i].w;
    }
    __shared__ float shS[8], shQ[8], bc[2];
    float rs = warp_sum(s), rq = warp_sum(ss);
    if ((threadIdx.x & 31) == 0) { shS[threadIdx.x >> 5] = rs; shQ[threadIdx.x >> 5] = rq; }
    __syncthreads();
    if (threadIdx.x == 0) {
        float ts = 0.f, tq = 0.f;
        for (int i = 0; i < 8; i++) { ts += shS[i]; tq += shQ[i]; }
        float mu  = ts * (1.f / (float)DI);
        float var = tq * (1.f / (float)DI) - mu * mu;
        bc[0] = mu;
        bc[1] = rsqrtf(var + 1e-5f);
    }
    __syncthreads();
    const float mu = bc[0], rstd = bc[1];
    __half2* o = (__half2*)(g_xn + (size_t)row * DI);
#pragma unroll
    for (int i = 0; i < 4; i++) {
        int idx = threadIdx.x + i * 256;
        float4 t = v[i];
        o[2 * idx]     = __floats2half2_rn((t.x - mu) * rstd, (t.y - mu) * rstd);
        o[2 * idx + 1] = __floats2half2_rn((t.z - mu) * rstd, (t.w - mu) * rstd);
    }
}

// ---------------- PTX helpers (baseline sm_80-class only) ----------------
__device__ __forceinline__ uint32_t smem_u32(const void* p) {
    uint32_t a;
    asm("{ .reg .u64 t; cvta.to.shared.u64 t, %1; cvt.u32.u64 %0, t; }" : "=r"(a) : "l"(p));
    return a;
}
__device__ __forceinline__ void cpa16(uint32_t d, const void* g) {
    asm volatile("cp.async.cg.shared.global [%0], [%1], 16;" :: "r"(d), "l"(g) : "memory");
}
#define CP_COMMIT() asm volatile("cp.async.commit_group;" ::: "memory")
#define CP_WAIT1()  asm volatile("cp.async.wait_group 1;" ::: "memory")

__device__ __forceinline__ void ldsm4(uint32_t* r, uint32_t a) {
    asm volatile("ldmatrix.sync.aligned.m8n8.x4.shared.b16 {%0,%1,%2,%3}, [%4];"
                 : "=r"(r[0]), "=r"(r[1]), "=r"(r[2]), "=r"(r[3]) : "r"(a));
}
__device__ __forceinline__ void mma16816(float* c, const uint32_t* a, const uint32_t* b) {
    asm volatile("mma.sync.aligned.m16n8k16.row.col.f32.f16.f16.f32 "
                 "{%0,%1,%2,%3}, {%4,%5,%6,%7}, {%8,%9}, {%0,%1,%2,%3};"
                 : "+f"(c[0]), "+f"(c[1]), "+f"(c[2]), "+f"(c[3])
                 : "r"(a[0]), "r"(a[1]), "r"(a[2]), "r"(a[3]), "r"(b[0]), "r"(b[1]));
}

// ---------------- GEMM ----------------
__device__ __forceinline__ void load_stage(uint32_t sb, int s,
                                           const __half* Abase, const __half* Bbase,
                                           int chunk, int tid) {
    const uint32_t stA = sb + (uint32_t)s * STAGE_BYTES;
    const uint32_t stB = stA + A_BYTES;
    const size_t kb = (size_t)chunk * BK;
#pragma unroll
    for (int it = 0; it < 12; it++) {
        int i = tid + it * 256;
        if (i < BM * 8) {                 // A: 128 rows x 8 segments(16B)
            int r = i >> 3, cs = i & 7;
            const void* g = Abase + (size_t)r * DI + kb + cs * 8;
            uint32_t off = (uint32_t)(r * 128 + cs * 16);
            cpa16(stA + (off ^ ((uint32_t)(r & 7) << 4)), g);
        } else {                          // B: 256 rows x 8 segments
            int j = i - BM * 8;
            int r = j >> 3, cs = j & 7;
            const void* g = Bbase + (size_t)r * DI + kb + cs * 8;
            uint32_t off = (uint32_t)(r * 128 + cs * 16);
            cpa16(stB + (off ^ ((uint32_t)(r & 7) << 4)), g);
        }
    }
    CP_COMMIT();
}

__global__ void __launch_bounds__(256, 1) k_gemm(float* __restrict__ out) {
    extern __shared__ char smem[];
    const uint32_t sb = smem_u32(smem);
    const int tid = threadIdx.x;
    const int wid = tid >> 5, lane = tid & 31;
    const int wm = wid >> 2, wn = wid & 3;           // warp grid 2(M) x 4(N), warp tile 64x64
    const int lr = lane & 7, sel = lane >> 3;
    const int g = lane >> 2, tc = lane & 3;

    // CTA swizzle: groups of 8 m-tiles x 16 n-tiles (128 CTAs ~ 1 wave) for L2 reuse
    const int grp = blockIdx.x >> 7;
    const int rem = blockIdx.x & 127;
    const int mt = grp * 8 + (rem & 7);              // 0..63
    const int nt = rem >> 3;                         // 0..15

    const __half* Abase = g_xn + (size_t)mt * BM * DI;
    const __half* Bbase = g_wb + (size_t)nt * BN * DI;

    float acc[4][8][4];
#pragma unroll
    for (int i = 0; i < 4; i++)
#pragma unroll
        for (int j = 0; j < 8; j++)
#pragma unroll
            for (int k = 0; k < 4; k++) acc[i][j][k] = 0.f;

    // Per-thread ldmatrix address components
    // A frag (m16k16): sel0:(row lr,   k+0) sel1:(row lr+8, k+0) sel2:(row lr, k+8) sel3:(row lr+8, k+8)
    const int a_row = wm * 64 + lr + (sel & 1) * 8;
    const uint32_t a_k2 = (uint32_t)((sel >> 1) * 16);      // bytes
    // B frag (k16n8, [n][k] smem): sel0:(n lr, k0) sel1:(n lr, k8) sel2:(n lr+8, k0) sel3:(n lr+8, k8)
    const int b_row = wn * 64 + lr + (sel >> 1) * 8;
    const uint32_t b_k2 = (uint32_t)((sel & 1) * 16);       // bytes
    const uint32_t xr = (uint32_t)lr << 4;

    // prologue
    load_stage(sb, 0, Abase, Bbase, 0, tid);
    load_stage(sb, 1, Abase, Bbase, 1, tid);

    int s = 0;
    for (int ks = 0; ks < NCHUNK; ks++) {
        CP_WAIT1();
        __syncthreads();

        {   // issue next-stage loads (always commit a group to keep wait bookkeeping exact)
            const int nxt = ks + 2;
            if (nxt < NCHUNK) {
                int sn = s + 2; if (sn >= NSTG) sn -= NSTG;
                load_stage(sb, sn, Abase, Bbase, nxt, tid);
            } else {
                CP_COMMIT();
            }
        }

        const uint32_t sA = sb + (uint32_t)s * STAGE_BYTES;
        const uint32_t sB = sA + A_BYTES;
#pragma unroll
        for (int kk = 0; kk < 4; kk++) {             // 4 ksteps of 16 within BK=64
            uint32_t a[4][4];
#pragma unroll
            for (int i = 0; i < 4; i++) {
                uint32_t col2 = (uint32_t)(kk * 32) + a_k2;
                uint32_t addr = sA + (uint32_t)(a_row + i * 16) * 128 + (col2 ^ xr);
                ldsm4(a[i], addr);
            }
            uint32_t b[4][4];
#pragma unroll
            for (int p = 0; p < 4; p++) {            // each x4 covers 2 n-tiles (16 n rows)
                uint32_t col2 = (uint32_t)(kk * 32) + b_k2;
                uint32_t addr = sB + (uint32_t)(b_row + p * 16) * 128 + (col2 ^ xr);
                ldsm4(b[p], addr);
            }
#pragma unroll
            for (int i = 0; i < 4; i++)
#pragma unroll
                for (int j = 0; j < 8; j++)
                    mma16816(acc[i][j], a[i], &b[j >> 1][(j & 1) * 2]);
        }

        s++; if (s == NSTG) s = 0;
    }

    // epilogue
    const float beta = g_beta;
    const int rbase = mt * BM + wm * 64 + g;
    const int cbase = nt * BN + wn * 64 + tc * 2;
#pragma unroll
    for (int i = 0; i < 4; i++) {
#pragma unroll
        for (int j = 0; j < 8; j++) {
            const int row = rbase + i * 16;
            const int col = cbase + j * 8;
            float2 v0 = make_float2(acc[i][j][0] * beta, acc[i][j][1] * beta);
            float2 v1 = make_float2(acc[i][j][2] * beta, acc[i][j][3] * beta);
            *(float2*)(out + (size_t)row * NOUT + col)       = v0;
            *(float2*)(out + (size_t)(row + 8) * NOUT + col) = v1;
        }
    }
}

// ---------------- launch ----------------
extern "C" void kernel_launch(void* const* d_in, const int* in_sizes, int n_in,
                              void* d_out, int out_size) {
    (void)in_sizes; (void)n_in; (void)out_size;
    const float* x = (const float*)d_in[0];
    const float* w = (const float*)d_in[1];
    float* out = (float*)d_out;

    cudaFuncSetAttribute(k_gemm, cudaFuncAttributeMaxDynamicSharedMemorySize, SMEM_TOTAL);

    k_wsum<<<2048, 256>>>(w);
    k_reduce_mean<<<1, 256>>>();
    k_binabs<<<2048, 256>>>(w);
    k_reduce_beta<<<1, 256>>>();
    k_ln<<<MROWS, 256>>>(x);
    k_gemm<<<(MROWS / BM) * (NOUT / BN), 256, SMEM_TOTAL>>>(out);
}

// round 6
// speedup vs baseline: 1.0394x; 1.0394x over previous
#include <cuda_runtime.h>
#include <cuda_fp16.h>
#include <cstdint>
#include <cstddef>

// Problem dims
#define DI    4096
#define MROWS 8192          // 4*2048
#define NOUT  4096
#define WN    (4096*4096)

// GEMM tiling (legacy mma.sync path — tcgen05 unavailable at compute_103)
#define BM 128
#define BN 256
#define BK 64               // 64 fp16 = 128B rows -> conflict-free xor swizzle
#define NSTG 3
#define NCHUNK (DI/BK)      // 64
#define A_BYTES (BM*BK*2)   // 16384
#define B_BYTES (BN*BK*2)   // 32768
#define STAGE_BYTES (A_BYTES + B_BYTES)          // 49152
#define SMEM_TOTAL (NSTG*STAGE_BYTES)            // 147456
#define NTHR 512

#define WSUM_BLOCKS 512
#define BIN_BLOCKS  2048

// Scratch (no cudaMalloc allowed)
__device__ __half g_xn[(size_t)MROWS * DI];   // 64 MB fp16 layernormed x
__device__ __half g_wb[(size_t)WN];           // 32 MB fp16 binarized weight
__device__ float  g_part1[WSUM_BLOCKS];
__device__ float  g_part2[BIN_BLOCKS];
__device__ float  g_wmean;
__device__ float  g_beta;
__device__ unsigned g_ctr1 = 0;
__device__ unsigned g_ctr2 = 0;

// ---------------- reduction helpers ----------------
__device__ __forceinline__ float warp_sum(float v) {
#pragma unroll
    for (int o = 16; o > 0; o >>= 1) v += __shfl_xor_sync(0xFFFFFFFFu, v, o);
    return v;
}

__device__ __forceinline__ float block_sum256(float v) {
    __shared__ float sh[8];
    float s = warp_sum(v);
    if ((threadIdx.x & 31) == 0) sh[threadIdx.x >> 5] = s;
    __syncthreads();
    float t = 0.f;
    if (threadIdx.x == 0) {
#pragma unroll
        for (int i = 0; i < 8; i++) t += sh[i];
    }
    return t;   // valid on thread 0 only
}

// ---------------- k1: LayerNorm rows + W-sum partials + mean (fused) ----------------
__global__ void k_ln_wsum(const float* __restrict__ x, const float* __restrict__ w) {
    if (blockIdx.x < MROWS) {
        // ---- LayerNorm one row ----
        const int row = blockIdx.x;
        const float4* xr = (const float4*)(x + (size_t)row * DI);
        float4 v[4];
        float s = 0.f, ss = 0.f;
#pragma unroll
        for (int i = 0; i < 4; i++) {
            v[i] = xr[threadIdx.x + i * 256];
            s  += v[i].x + v[i].y + v[i].z + v[i].w;
            ss += v[i].x * v[i].x + v[i].y * v[i].y + v[i].z * v[i].z + v[i].w * v[i].w;
        }
        __shared__ float shS[8], shQ[8], bc[2];
        float rs = warp_sum(s), rq = warp_sum(ss);
        if ((threadIdx.x & 31) == 0) { shS[threadIdx.x >> 5] = rs; shQ[threadIdx.x >> 5] = rq; }
        __syncthreads();
        if (threadIdx.x == 0) {
            float ts = 0.f, tq = 0.f;
#pragma unroll
            for (int i = 0; i < 8; i++) { ts += shS[i]; tq += shQ[i]; }
            float mu  = ts * (1.f / (float)DI);
            float var = tq * (1.f / (float)DI) - mu * mu;
            bc[0] = mu;
            bc[1] = rsqrtf(var + 1e-5f);
        }
        __syncthreads();
        const float mu = bc[0], rstd = bc[1];
        __half2* o = (__half2*)(g_xn + (size_t)row * DI);
#pragma unroll
        for (int i = 0; i < 4; i++) {
            int idx = threadIdx.x + i * 256;
            float4 t = v[i];
            o[2 * idx]     = __floats2half2_rn((t.x - mu) * rstd, (t.y - mu) * rstd);
            o[2 * idx + 1] = __floats2half2_rn((t.z - mu) * rstd, (t.w - mu) * rstd);
        }
    } else {
        // ---- W-sum partials ----
        const int b = blockIdx.x - MROWS;
        float s = 0.f;
        const float4* w4 = (const float4*)w;
        for (int i = b * 256 + threadIdx.x; i < WN / 4; i += WSUM_BLOCKS * 256) {
            float4 v = w4[i];
            s += v.x + v.y + v.z + v.w;
        }
        float t = block_sum256(s);
        if (threadIdx.x == 0) g_part1[b] = t;
    }

    // ---- last-block final reduction of mean (deterministic fixed-order) ----
    __shared__ unsigned done;
    __threadfence();
    __syncthreads();
    if (threadIdx.x == 0) done = atomicAdd(&g_ctr1, 1u);
    __syncthreads();
    if (done == (unsigned)(MROWS + WSUM_BLOCKS - 1)) {
        float s = 0.f;
        for (int i = threadIdx.x; i < WSUM_BLOCKS; i += 256) s += g_part1[i];
        float t = block_sum256(s);
        if (threadIdx.x == 0) {
            g_wmean = t / (float)WN;
            g_ctr1 = 0;         // reset for next graph replay
            __threadfence();
        }
    }
}

// ---------------- k2: binarize W + |.| partials + beta (fused) ----------------
__global__ void k_binabs_beta(const float* __restrict__ w) {
    const float m = g_wmean;
    float s = 0.f;
    const float4* w4 = (const float4*)w;
    __half2* o = (__half2*)g_wb;
    for (int i = blockIdx.x * 256 + threadIdx.x; i < WN / 4; i += BIN_BLOCKS * 256) {
        float4 v = w4[i];
        float a = v.x - m, b = v.y - m, c = v.z - m, d = v.w - m;
        s += fabsf(a) + fabsf(b) + fabsf(c) + fabsf(d);
        float sa = (a > 0.f) ? 1.f : ((a < 0.f) ? -1.f : 0.f);
        float sb = (b > 0.f) ? 1.f : ((b < 0.f) ? -1.f : 0.f);
        float sc = (c > 0.f) ? 1.f : ((c < 0.f) ? -1.f : 0.f);
        float sd = (d > 0.f) ? 1.f : ((d < 0.f) ? -1.f : 0.f);
        o[2 * i]     = __floats2half2_rn(sa, sb);
        o[2 * i + 1] = __floats2half2_rn(sc, sd);
    }
    float t = block_sum256(s);
    if (threadIdx.x == 0) g_part2[blockIdx.x] = t;

    __shared__ unsigned done;
    __threadfence();
    __syncthreads();
    if (threadIdx.x == 0) done = atomicAdd(&g_ctr2, 1u);
    __syncthreads();
    if (done == (unsigned)(BIN_BLOCKS - 1)) {
        float s2 = 0.f;
        for (int i = threadIdx.x; i < BIN_BLOCKS; i += 256) s2 += g_part2[i];
        float t2 = block_sum256(s2);
        if (threadIdx.x == 0) {
            g_beta = t2 / (float)WN;
            g_ctr2 = 0;
            __threadfence();
        }
    }
}

// ---------------- PTX helpers (baseline sm_80-class only) ----------------
__device__ __forceinline__ uint32_t smem_u32(const void* p) {
    uint32_t a;
    asm("{ .reg .u64 t; cvta.to.shared.u64 t, %1; cvt.u32.u64 %0, t; }" : "=r"(a) : "l"(p));
    return a;
}
__device__ __forceinline__ void cpa16(uint32_t d, const void* g) {
    asm volatile("cp.async.cg.shared.global [%0], [%1], 16;" :: "r"(d), "l"(g) : "memory");
}
#define CP_COMMIT() asm volatile("cp.async.commit_group;" ::: "memory")
#define CP_WAIT1()  asm volatile("cp.async.wait_group 1;" ::: "memory")

__device__ __forceinline__ void ldsm4(uint32_t* r, uint32_t a) {
    asm volatile("ldmatrix.sync.aligned.m8n8.x4.shared.b16 {%0,%1,%2,%3}, [%4];"
                 : "=r"(r[0]), "=r"(r[1]), "=r"(r[2]), "=r"(r[3]) : "r"(a));
}
__device__ __forceinline__ void mma16816(float* c, const uint32_t* a, const uint32_t* b) {
    asm volatile("mma.sync.aligned.m16n8k16.row.col.f32.f16.f16.f32 "
                 "{%0,%1,%2,%3}, {%4,%5,%6,%7}, {%8,%9}, {%0,%1,%2,%3};"
                 : "+f"(c[0]), "+f"(c[1]), "+f"(c[2]), "+f"(c[3])
                 : "r"(a[0]), "r"(a[1]), "r"(a[2]), "r"(a[3]), "r"(b[0]), "r"(b[1]));
}

// ---------------- GEMM ----------------
__device__ __forceinline__ void load_stage(uint32_t sb, int s,
                                           const __half* Abase, const __half* Bbase,
                                           int chunk, int tid) {
    const uint32_t stA = sb + (uint32_t)s * STAGE_BYTES;
    const uint32_t stB = stA + A_BYTES;
    const size_t kb = (size_t)chunk * BK;
#pragma unroll
    for (int it = 0; it < 6; it++) {
        int i = tid + it * NTHR;
        if (i < BM * 8) {                 // A: 128 rows x 8 segments(16B)
            int r = i >> 3, cs = i & 7;
            const void* g = Abase + (size_t)r * DI + kb + cs * 8;
            uint32_t off = (uint32_t)(r * 128 + cs * 16);
            cpa16(stA + (off ^ ((uint32_t)(r & 7) << 4)), g);
        } else {                          // B: 256 rows x 8 segments
            int j = i - BM * 8;
            int r = j >> 3, cs = j & 7;
            const void* g = Bbase + (size_t)r * DI + kb + cs * 8;
            uint32_t off = (uint32_t)(r * 128 + cs * 16);
            cpa16(stB + (off ^ ((uint32_t)(r & 7) << 4)), g);
        }
    }
    CP_COMMIT();
}

__global__ void __launch_bounds__(NTHR, 1) k_gemm(float* __restrict__ out) {
    extern __shared__ char smem[];
    const uint32_t sb = smem_u32(smem);
    const int tid = threadIdx.x;
    const int wid = tid >> 5, lane = tid & 31;
    const int wm = wid >> 2, wn = wid & 3;           // warp grid 4(M) x 4(N), warp tile 32x64
    const int lr = lane & 7, sel = lane >> 3;
    const int g = lane >> 2, tc = lane & 3;

    // CTA swizzle: groups of 8 m-tiles x 16 n-tiles (128 CTAs ~ 1 wave) for L2 reuse
    const int grp = blockIdx.x >> 7;
    const int rem = blockIdx.x & 127;
    const int mt = grp * 8 + (rem & 7);              // 0..63
    const int nt = rem >> 3;                         // 0..15

    const __half* Abase = g_xn + (size_t)mt * BM * DI;
    const __half* Bbase = g_wb + (size_t)nt * BN * DI;

    float acc[2][8][4];
#pragma unroll
    for (int i = 0; i < 2; i++)
#pragma unroll
        for (int j = 0; j < 8; j++)
#pragma unroll
            for (int k = 0; k < 4; k++) acc[i][j][k] = 0.f;

    // A frag (m16k16 per ldsm4): rows wm*32 + lr + (sel&1)*8 + i*16, k-half (sel>>1)*16B
    const int a_row = wm * 32 + lr + (sel & 1) * 8;
    const uint32_t a_k2 = (uint32_t)((sel >> 1) * 16);      // bytes
    // B frag (k16n16 per ldsm4, [n][k] smem): n rows wn*64 + lr + (sel>>1)*8 + p*16, k-half (sel&1)*16B
    const int b_row = wn * 64 + lr + (sel >> 1) * 8;
    const uint32_t b_k2 = (uint32_t)((sel & 1) * 16);       // bytes
    const uint32_t xr = (uint32_t)lr << 4;

    // prologue
    load_stage(sb, 0, Abase, Bbase, 0, tid);
    load_stage(sb, 1, Abase, Bbase, 1, tid);

    int s = 0;
    for (int ks = 0; ks < NCHUNK; ks++) {
        CP_WAIT1();
        __syncthreads();

        {   // issue next-stage loads (always commit a group to keep wait bookkeeping exact)
            const int nxt = ks + 2;
            if (nxt < NCHUNK) {
                int sn = s + 2; if (sn >= NSTG) sn -= NSTG;
                load_stage(sb, sn, Abase, Bbase, nxt, tid);
            } else {
                CP_COMMIT();
            }
        }

        const uint32_t sA = sb + (uint32_t)s * STAGE_BYTES;
        const uint32_t sB = sA + A_BYTES;
#pragma unroll
        for (int kk = 0; kk < 4; kk++) {             // 4 ksteps of 16 within BK=64
            const uint32_t col2 = (uint32_t)(kk * 32);
            uint32_t a[2][4];
#pragma unroll
            for (int i = 0; i < 2; i++) {
                uint32_t addr = sA + (uint32_t)(a_row + i * 16) * 128 + ((col2 + a_k2) ^ xr);
                ldsm4(a[i], addr);
            }
            uint32_t b[4][4];
#pragma unroll
            for (int p = 0; p < 4; p++) {            // each x4 covers 16 n-rows
                uint32_t addr = sB + (uint32_t)(b_row + p * 16) * 128 + ((col2 + b_k2) ^ xr);
                ldsm4(b[p], addr);
            }
#pragma unroll
            for (int i = 0; i < 2; i++)
#pragma unroll
                for (int j = 0; j < 8; j++)
                    mma16816(acc[i][j], a[i], &b[j >> 1][(j & 1) * 2]);
        }

        s++; if (s == NSTG) s = 0;
    }

    // epilogue
    const float beta = g_beta;
    const int rbase = mt * BM + wm * 32 + g;
    const int cbase = nt * BN + wn * 64 + tc * 2;
#pragma unroll
    for (int i = 0; i < 2; i++) {
#pragma unroll
        for (int j = 0; j < 8; j++) {
            const int row = rbase + i * 16;
            const int col = cbase + j * 8;
            float2 v0 = make_float2(acc[i][j][0] * beta, acc[i][j][1] * beta);
            float2 v1 = make_float2(acc[i][j][2] * beta, acc[i][j][3] * beta);
            *(float2*)(out + (size_t)row * NOUT + col)       = v0;
            *(float2*)(out + (size_t)(row + 8) * NOUT + col) = v1;
        }
    }
}

// ---------------- launch ----------------
extern "C" void kernel_launch(void* const* d_in, const int* in_sizes, int n_in,
                              void* d_out, int out_size) {
    (void)in_sizes; (void)n_in; (void)out_size;
    const float* x = (const float*)d_in[0];
    const float* w = (const float*)d_in[1];
    float* out = (float*)d_out;

    cudaFuncSetAttribute(k_gemm, cudaFuncAttributeMaxDynamicSharedMemorySize, SMEM_TOTAL);

    k_ln_wsum<<<MROWS + WSUM_BLOCKS, 256>>>(x, w);
    k_binabs_beta<<<BIN_BLOCKS, 256>>>(w);
    k_gemm<<<(MROWS / BM) * (NOUT / BN), NTHR, SMEM_TOTAL>>>(out);
}